// round 14
// baseline (speedup 1.0000x reference)
#include <cuda_runtime.h>
#include <cuda_fp16.h>
#include <mma.h>
using namespace nvcuda;

#define NN 50000
#define NPAD 50048     // NN rounded up to 128 (GEMM tile)
#define EE 800000
#define TT (EE + NN)
#define HH 4
#define CHN 256        // H * C (both layers)
#define C2  64
#define SCAN_BLKS 196  // 196*256 = 50176 >= NN
#define SPLIT_N 25088  // node/row split: 196 GEMM m-blocks
#define SPLIT_B 196    // gemm blocks in chunk A (391 total)

// ---------------- scratch (device globals; no allocation allowed) ----------
__device__ __align__(16) __half g_h16[(size_t)NPAD * CHN];  // GEMM out (fp16)
__device__ __align__(16) __half g_x1h[(size_t)NPAD * CHN];  // relu(layer1 out), fp16
__device__ __align__(16) float g_as[NN * HH];
__device__ __align__(16) float g_ad[NN * HH];
__device__ __align__(16) float g_e[(size_t)TT * HH];        // CSR-ordered logits
__device__ int   g_deg[NN];
__device__ int   g_pref[NN];
__device__ int   g_bsum[SCAN_BLKS];
__device__ int   g_boff[SCAN_BLKS];
__device__ int   g_rowptr[NN + 1];
__device__ int   g_cursor[NN];
__device__ int   g_srcs[TT];

// ---------------- streams for fork/join overlap (static init, never freed) --
struct StreamsInit {
    cudaStream_t s2;
    cudaEvent_t fork, join, evA, evB;
    StreamsInit() {
        cudaStreamCreateWithFlags(&s2, cudaStreamNonBlocking);
        cudaEventCreateWithFlags(&fork, cudaEventDisableTiming);
        cudaEventCreateWithFlags(&join, cudaEventDisableTiming);
        cudaEventCreateWithFlags(&evA, cudaEventDisableTiming);
        cudaEventCreateWithFlags(&evB, cudaEventDisableTiming);
    }
};
static StreamsInit g_str;

// ---------------- CSR build -------------------------------------------------
__global__ void k_zero_deg() {
    int i = blockIdx.x * blockDim.x + threadIdx.x;
    if (i < NN) g_deg[i] = 0;
}

__global__ void k_hist(const int* __restrict__ ei) {
    int t = blockIdx.x * blockDim.x + threadIdx.x;
    if (t >= TT) return;
    int d = (t < EE) ? ei[EE + t] : (t - EE);
    atomicAdd(&g_deg[d], 1);
}

__global__ void k_scan1() {
    __shared__ int s[256];
    const int tid = threadIdx.x;
    const int i = blockIdx.x * 256 + tid;
    int v = (i < NN) ? g_deg[i] : 0;
    s[tid] = v;
    __syncthreads();
#pragma unroll
    for (int off = 1; off < 256; off <<= 1) {
        int t = (tid >= off) ? s[tid - off] : 0;
        __syncthreads();
        s[tid] += t;
        __syncthreads();
    }
    if (i < NN) g_pref[i] = s[tid] - v;
    if (tid == 255) g_bsum[blockIdx.x] = s[255];
}

__global__ void k_scan2() {
    __shared__ int s[SCAN_BLKS];
    const int tid = threadIdx.x;
    int v = (tid < SCAN_BLKS) ? g_bsum[tid] : 0;
    if (tid < SCAN_BLKS) s[tid] = v;
    __syncthreads();
    for (int off = 1; off < SCAN_BLKS; off <<= 1) {
        int t = (tid >= off && tid < SCAN_BLKS) ? s[tid - off] : 0;
        __syncthreads();
        if (tid < SCAN_BLKS) s[tid] += t;
        __syncthreads();
    }
    if (tid < SCAN_BLKS) g_boff[tid] = s[tid] - v;
    if (tid == SCAN_BLKS - 1) g_rowptr[NN] = s[SCAN_BLKS - 1];
}

__global__ void k_scan3() {
    const int i = blockIdx.x * 256 + threadIdx.x;
    if (i < NN) {
        int r = g_pref[i] + g_boff[blockIdx.x];
        g_rowptr[i] = r;
        g_cursor[i] = r;
    }
}

__global__ void k_scatter(const int* __restrict__ ei) {
    int t = blockIdx.x * blockDim.x + threadIdx.x;
    if (t >= TT) return;
    int sv, dv;
    if (t < EE) { sv = ei[t]; dv = ei[EE + t]; }
    else        { sv = dv = t - EE; }
    int pos = atomicAdd(&g_cursor[dv], 1);
    g_srcs[pos] = sv;
}

// ---------------- fp16 tensor-core GEMM + fused alpha/fp16 epilogue ---------
// BM=128, BN=128, BK=32; double-buffered fp16 smem; 8 warps 4x2; warp 32x64.
// mblk0: row-block offset (row chunking for pipelining).
#define BM 128
#define BN 128
#define BK 32
#define LDAH (BK + 8)
#define LDBH (BN + 8)
#define ASZH (BM * LDAH)
#define BSZH (BK * LDBH)
#define LDC  (64 + 4)
#define SMEM_BYTES (2 * (ASZH + BSZH) * 2)

template <int LAYER>
__global__ void __launch_bounds__(256) k_gemm(const float* __restrict__ Aext,
                                              const float* __restrict__ B,
                                              const float* __restrict__ att_s,
                                              const float* __restrict__ att_d,
                                              int M, int K, int mblk0) {
    __shared__ __align__(16) char smbuf[SMEM_BYTES];
    __half* Ash = (__half*)smbuf;
    __half* Bsh = (__half*)(smbuf + 2 * ASZH * 2);

    const int tid = threadIdx.x;
    const int wid = tid >> 5;
    const int wm = wid >> 1;
    const int wn = wid & 1;
    const int m0 = (blockIdx.y + mblk0) * BM;
    const int n0 = blockIdx.x * BN;

    const int brow[4] = { (tid + 0) >> 5, (tid + 256) >> 5, (tid + 512) >> 5, (tid + 768) >> 5 };
    const int bcol = (tid & 31) * 4;
    float4 rbf[4];

    const int arow_f[4] = { (tid + 0) >> 3, (tid + 256) >> 3, (tid + 512) >> 3, (tid + 768) >> 3 };
    const int acol_f = (tid & 7) * 4;
    float4 raf[4];
    const int arow_h[2] = { (tid + 0) >> 2, (tid + 256) >> 2 };
    const int acol_h = (tid & 3) * 8;
    uint4 rah[2];

    auto loadG = [&](int k0) {
        if (LAYER == 1) {
#pragma unroll
            for (int i = 0; i < 4; i++) {
                float4 v = make_float4(0.f, 0.f, 0.f, 0.f);
                if (m0 + arow_f[i] < M)
                    v = *(const float4*)&Aext[(size_t)(m0 + arow_f[i]) * K + k0 + acol_f];
                raf[i] = v;
            }
        } else {
#pragma unroll
            for (int i = 0; i < 2; i++)
                rah[i] = *(const uint4*)&g_x1h[(size_t)(m0 + arow_h[i]) * K + k0 + acol_h];
        }
#pragma unroll
        for (int i = 0; i < 4; i++)
            rbf[i] = *(const float4*)&B[(size_t)(k0 + brow[i]) * CHN + n0 + bcol];
    };
    auto storeS = [&](int buf) {
        if (LAYER == 1) {
#pragma unroll
            for (int i = 0; i < 4; i++) {
                __half2* p = (__half2*)&Ash[buf * ASZH + arow_f[i] * LDAH + acol_f];
                p[0] = __floats2half2_rn(raf[i].x, raf[i].y);
                p[1] = __floats2half2_rn(raf[i].z, raf[i].w);
            }
        } else {
#pragma unroll
            for (int i = 0; i < 2; i++)
                *(uint4*)&Ash[buf * ASZH + arow_h[i] * LDAH + acol_h] = rah[i];
        }
#pragma unroll
        for (int i = 0; i < 4; i++) {
            __half2* p = (__half2*)&Bsh[buf * BSZH + brow[i] * LDBH + bcol];
            p[0] = __floats2half2_rn(rbf[i].x, rbf[i].y);
            p[1] = __floats2half2_rn(rbf[i].z, rbf[i].w);
        }
    };

    wmma::fragment<wmma::accumulator, 16, 16, 16, float> c[2][4];
#pragma unroll
    for (int i = 0; i < 2; i++)
#pragma unroll
        for (int j = 0; j < 4; j++) wmma::fill_fragment(c[i][j], 0.f);

    loadG(0);
    storeS(0);
    __syncthreads();

    int buf = 0;
    for (int k0 = 0; k0 < K; k0 += BK) {
        const bool has_next = (k0 + BK) < K;
        if (has_next) loadG(k0 + BK);

#pragma unroll
        for (int kk = 0; kk < BK; kk += 16) {
            wmma::fragment<wmma::matrix_a, 16, 16, 16, __half, wmma::row_major> a[2];
            wmma::fragment<wmma::matrix_b, 16, 16, 16, __half, wmma::row_major> b[4];
#pragma unroll
            for (int i = 0; i < 2; i++)
                wmma::load_matrix_sync(a[i], &Ash[buf * ASZH + (wm * 32 + i * 16) * LDAH + kk], LDAH);
#pragma unroll
            for (int j = 0; j < 4; j++)
                wmma::load_matrix_sync(b[j], &Bsh[buf * BSZH + kk * LDBH + wn * 64 + j * 16], LDBH);
#pragma unroll
            for (int i = 0; i < 2; i++)
#pragma unroll
                for (int j = 0; j < 4; j++)
                    wmma::mma_sync(c[i][j], a[i], b[j], c[i][j]);
        }

        if (has_next) {
            storeS(buf ^ 1);
            __syncthreads();
            buf ^= 1;
        }
    }

    // ---- epilogue: two 64-col chunks (each = one head) through smem ----
    float* Cs = (float*)smbuf;
    const int r = tid >> 1;
    const int half = tid & 1;
#pragma unroll
    for (int chunk = 0; chunk < 2; chunk++) {
        __syncthreads();
        if (wn == chunk) {
#pragma unroll
            for (int i = 0; i < 2; i++)
#pragma unroll
                for (int j = 0; j < 4; j++)
                    wmma::store_matrix_sync(
                        &Cs[(wm * 32 + i * 16) * LDC + j * 16],
                        c[i][j], LDC, wmma::mem_row_major);
        }
        __syncthreads();

        const float* crow = &Cs[r * LDC + half * 32];
        const int nbase = n0 + chunk * 64;

        uint4 w[4];
        __half2* wh = (__half2*)w;
#pragma unroll
        for (int i = 0; i < 16; i++)
            wh[i] = __floats2half2_rn(crow[2 * i], crow[2 * i + 1]);
        uint4* dst = (uint4*)&g_h16[(size_t)(m0 + r) * CHN + nbase + half * 32];
#pragma unroll
        for (int i = 0; i < 4; i++) dst[i] = w[i];

        const int hh = nbase >> 6;
        const float* asp = att_s + nbase + half * 32;
        const float* adp = att_d + nbase + half * 32;
        float s = 0.f, d = 0.f;
#pragma unroll
        for (int cc = 0; cc < 32; cc++) {
            float v = crow[cc];
            s += v * asp[cc];
            d += v * adp[cc];
        }
        s += __shfl_xor_sync(0xffffffffu, s, 1);
        d += __shfl_xor_sync(0xffffffffu, d, 1);
        if (half == 0 && m0 + r < NN) {
            g_as[(m0 + r) * 4 + hh] = s;
            g_ad[(m0 + r) * 4 + hh] = d;
        }
    }
}

// ---------------- fused edge + online-softmax + aggregation (warp/node) -----
__device__ __forceinline__ float lrelu(float v) { return v > 0.f ? v : 0.2f * v; }

__device__ __forceinline__ void online_upd(float& m, float& s, float e) {
    float mn = fmaxf(m, e);
    s = s * __expf(m - mn) + __expf(e - mn);
    m = mn;
}
__device__ __forceinline__ void online_red(float& m, float& s, int o) {
    float mo = __shfl_xor_sync(0xffffffffu, m, o);
    float so = __shfl_xor_sync(0xffffffffu, s, o);
    float mn = fmaxf(m, mo);
    s = s * __expf(m - mn) + so * __expf(mo - mn);
    m = mn;
}

// nodes [n0base, n0base + nCount)
template <int LAYER>
__global__ void __launch_bounds__(256) k_agg(const float* __restrict__ bias,
                                             float* __restrict__ outext,
                                             int n0base, int nCount) {
    const int w = (blockIdx.x * blockDim.x + threadIdx.x) >> 5;
    const int lane = threadIdx.x & 31;
    if (w >= nCount) return;
    const int gw = n0base + w;
    const int row = g_rowptr[gw];
    const int deg = g_rowptr[gw + 1] - row;

    const float4 ad4 = *(const float4*)&g_ad[gw * 4];

    float4 m4 = make_float4(-1e30f, -1e30f, -1e30f, -1e30f);
    float4 s4 = make_float4(0.f, 0.f, 0.f, 0.f);
    for (int j = lane; j < deg; j += 32) {
        const int sv = g_srcs[row + j];
        const float4 as = *(const float4*)&g_as[sv * 4];
        float4 e;
        e.x = lrelu(as.x + ad4.x);
        e.y = lrelu(as.y + ad4.y);
        e.z = lrelu(as.z + ad4.z);
        e.w = lrelu(as.w + ad4.w);
        *(float4*)&g_e[(size_t)(row + j) * 4] = e;
        online_upd(m4.x, s4.x, e.x);
        online_upd(m4.y, s4.y, e.y);
        online_upd(m4.z, s4.z, e.z);
        online_upd(m4.w, s4.w, e.w);
    }
#pragma unroll
    for (int o = 16; o; o >>= 1) {
        online_red(m4.x, s4.x, o);
        online_red(m4.y, s4.y, o);
        online_red(m4.z, s4.z, o);
        online_red(m4.w, s4.w, o);
    }
    __syncwarp();

    const int head = lane >> 3;
    const float m = (head == 0) ? m4.x : (head == 1) ? m4.y : (head == 2) ? m4.z : m4.w;
    const float sd = (head == 0) ? s4.x : (head == 1) ? s4.y : (head == 2) ? s4.z : s4.w;
    const float inv = 1.f / (sd + 1e-16f);
    const int cb = lane * 8;

    float acc[8];
#pragma unroll
    for (int k = 0; k < 8; k++) acc[k] = 0.f;

#pragma unroll 2
    for (int j = 0; j < deg; j++) {
        const float e = g_e[(size_t)(row + j) * 4 + head];
        const int src = g_srcs[row + j];
        const float a = __expf(e - m) * inv;
        const uint4 u = *(const uint4*)&g_h16[(size_t)src * CHN + cb];
        const __half2* hp = (const __half2*)&u;
#pragma unroll
        for (int k = 0; k < 4; k++) {
            const float2 f = __half22float2(hp[k]);
            acc[2 * k]     += a * f.x;
            acc[2 * k + 1] += a * f.y;
        }
    }

    if (LAYER == 1) {
        const float4 b0 = *(const float4*)&bias[cb];
        const float4 b1 = *(const float4*)&bias[cb + 4];
        uint4 o;
        __half2* oh = (__half2*)&o;
        oh[0] = __floats2half2_rn(fmaxf(acc[0] + b0.x, 0.f), fmaxf(acc[1] + b0.y, 0.f));
        oh[1] = __floats2half2_rn(fmaxf(acc[2] + b0.z, 0.f), fmaxf(acc[3] + b0.w, 0.f));
        oh[2] = __floats2half2_rn(fmaxf(acc[4] + b1.x, 0.f), fmaxf(acc[5] + b1.y, 0.f));
        oh[3] = __floats2half2_rn(fmaxf(acc[6] + b1.z, 0.f), fmaxf(acc[7] + b1.w, 0.f));
        *(uint4*)&g_x1h[(size_t)gw * CHN + cb] = o;
    } else {
#pragma unroll
        for (int k = 0; k < 8; k++) {
            acc[k] += __shfl_xor_sync(0xffffffffu, acc[k], 8);
            acc[k] += __shfl_xor_sync(0xffffffffu, acc[k], 16);
        }
        if (lane < 8) {
            const int c = lane * 8;
            const float4 b0 = *(const float4*)&bias[c];
            const float4 b1 = *(const float4*)&bias[c + 4];
            float4 o0, o1;
            o0.x = 0.25f * acc[0] + b0.x;
            o0.y = 0.25f * acc[1] + b0.y;
            o0.z = 0.25f * acc[2] + b0.z;
            o0.w = 0.25f * acc[3] + b0.w;
            o1.x = 0.25f * acc[4] + b1.x;
            o1.y = 0.25f * acc[5] + b1.y;
            o1.z = 0.25f * acc[6] + b1.z;
            o1.w = 0.25f * acc[7] + b1.w;
            *(float4*)&outext[(size_t)gw * C2 + c] = o0;
            *(float4*)&outext[(size_t)gw * C2 + c + 4] = o1;
        }
    }
}

// ---------------- launch -----------------------------------------------------
extern "C" void kernel_launch(void* const* d_in, const int* in_sizes, int n_in,
                              void* d_out, int out_size) {
    const float* x   = (const float*)d_in[0];
    const int*   ei  = (const int*)d_in[1];
    const float* W1  = (const float*)d_in[2];
    const float* as1 = (const float*)d_in[3];
    const float* ad1 = (const float*)d_in[4];
    const float* b1  = (const float*)d_in[5];
    const float* W2  = (const float*)d_in[6];
    const float* as2 = (const float*)d_in[7];
    const float* ad2 = (const float*)d_in[8];
    const float* b2  = (const float*)d_in[9];
    float* out = (float*)d_out;

    dim3 gemm_grid_full(CHN / BN, NPAD / BM);          // (2, 391)
    dim3 gemm_grid_A(CHN / BN, SPLIT_B);               // rows [0, 25088)
    dim3 gemm_grid_B(CHN / BN, NPAD / BM - SPLIT_B);   // rows [25088, NPAD)

    const int aggA_blocks = (SPLIT_N * 32 + 255) / 256;
    const int aggB_blocks = ((NN - SPLIT_N) * 32 + 255) / 256;
    const int agg_blocks  = (NN * 32 + 255) / 256;

    // fork: GEMM-1 on side stream, CSR build on main stream (independent)
    cudaEventRecord(g_str.fork, 0);
    cudaStreamWaitEvent(g_str.s2, g_str.fork, 0);
    k_gemm<1><<<gemm_grid_full, 256, 0, g_str.s2>>>(x, W1, as1, ad1, NN, 128, 0);
    cudaEventRecord(g_str.join, g_str.s2);

    k_zero_deg<<<(NN + 255) / 256, 256>>>();
    k_hist<<<(TT + 255) / 256, 256>>>(ei);
    k_scan1<<<SCAN_BLKS, 256>>>();
    k_scan2<<<1, 256>>>();
    k_scan3<<<SCAN_BLKS, 256>>>();
    k_scatter<<<(TT + 255) / 256, 256>>>(ei);

    // join: agg<1> needs CSR (main) + GEMM-1 (s2)
    cudaStreamWaitEvent(0, g_str.join, 0);

    // pipelined layer-1 agg / layer-2 GEMM
    k_agg<1><<<aggA_blocks, 256>>>(b1, nullptr, 0, SPLIT_N);
    cudaEventRecord(g_str.evA, 0);
    cudaStreamWaitEvent(g_str.s2, g_str.evA, 0);
    k_gemm<2><<<gemm_grid_A, 256, 0, g_str.s2>>>(nullptr, W2, as2, ad2, NN, 256, 0);
    cudaEventRecord(g_str.evB, g_str.s2);

    k_agg<1><<<aggB_blocks, 256>>>(b1, nullptr, SPLIT_N, NN - SPLIT_N);
    k_gemm<2><<<gemm_grid_B, 256>>>(nullptr, W2, as2, ad2, NN, 256, SPLIT_B);

    // agg<2> needs gemm2_A (s2) + gemm2_B (main)
    cudaStreamWaitEvent(0, g_str.evB, 0);
    k_agg<2><<<agg_blocks, 256>>>(b2, out, 0, NN);
}

// round 15
// speedup vs baseline: 1.0370x; 1.0370x over previous
#include <cuda_runtime.h>
#include <cuda_fp16.h>
#include <mma.h>
using namespace nvcuda;

#define NN 50000
#define NPAD 50048     // NN rounded up to 128 (GEMM tile)
#define EE 800000
#define TT (EE + NN)
#define HH 4
#define CHN 256        // H * C (both layers)
#define C2  64
#define SCAN_BLKS 196  // 196*256 = 50176 >= NN
#define ECAP 64        // per-warp SMEM edge cache (spill to g_e beyond)

// ---------------- scratch (device globals; no allocation allowed) ----------
__device__ __align__(16) __half g_h16[(size_t)NPAD * CHN];  // GEMM out (fp16)
__device__ __align__(16) __half g_x1h[(size_t)NPAD * CHN];  // relu(layer1 out), fp16
__device__ __align__(16) float g_as[NN * HH];
__device__ __align__(16) float g_ad[NN * HH];
__device__ __align__(16) float g_e[(size_t)TT * HH];        // spill only (deg > ECAP)
__device__ int   g_deg[NN];
__device__ int   g_pref[NN];
__device__ int   g_bsum[SCAN_BLKS];
__device__ int   g_boff[SCAN_BLKS];
__device__ int   g_rowptr[NN + 1];
__device__ int   g_cursor[NN];
__device__ int   g_srcs[TT];

// ---------------- streams for fork/join overlap (static init, never freed) --
struct StreamsInit {
    cudaStream_t s2;
    cudaEvent_t fork, join;
    StreamsInit() {
        cudaStreamCreateWithFlags(&s2, cudaStreamNonBlocking);
        cudaEventCreateWithFlags(&fork, cudaEventDisableTiming);
        cudaEventCreateWithFlags(&join, cudaEventDisableTiming);
    }
};
static StreamsInit g_str;

// ---------------- CSR build -------------------------------------------------
__global__ void k_zero_deg() {
    int i = blockIdx.x * blockDim.x + threadIdx.x;
    if (i < NN) g_deg[i] = 0;
}

__global__ void k_hist(const int* __restrict__ ei) {
    int t = blockIdx.x * blockDim.x + threadIdx.x;
    if (t >= TT) return;
    int d = (t < EE) ? ei[EE + t] : (t - EE);
    atomicAdd(&g_deg[d], 1);
}

__global__ void k_scan1() {
    __shared__ int s[256];
    const int tid = threadIdx.x;
    const int i = blockIdx.x * 256 + tid;
    int v = (i < NN) ? g_deg[i] : 0;
    s[tid] = v;
    __syncthreads();
#pragma unroll
    for (int off = 1; off < 256; off <<= 1) {
        int t = (tid >= off) ? s[tid - off] : 0;
        __syncthreads();
        s[tid] += t;
        __syncthreads();
    }
    if (i < NN) g_pref[i] = s[tid] - v;
    if (tid == 255) g_bsum[blockIdx.x] = s[255];
}

__global__ void k_scan2() {
    __shared__ int s[SCAN_BLKS];
    const int tid = threadIdx.x;
    int v = (tid < SCAN_BLKS) ? g_bsum[tid] : 0;
    if (tid < SCAN_BLKS) s[tid] = v;
    __syncthreads();
    for (int off = 1; off < SCAN_BLKS; off <<= 1) {
        int t = (tid >= off && tid < SCAN_BLKS) ? s[tid - off] : 0;
        __syncthreads();
        if (tid < SCAN_BLKS) s[tid] += t;
        __syncthreads();
    }
    if (tid < SCAN_BLKS) g_boff[tid] = s[tid] - v;
    if (tid == SCAN_BLKS - 1) g_rowptr[NN] = s[SCAN_BLKS - 1];
}

__global__ void k_scan3() {
    const int i = blockIdx.x * 256 + threadIdx.x;
    if (i < NN) {
        int r = g_pref[i] + g_boff[blockIdx.x];
        g_rowptr[i] = r;
        g_cursor[i] = r;
    }
}

__global__ void k_scatter(const int* __restrict__ ei) {
    int t = blockIdx.x * blockDim.x + threadIdx.x;
    if (t >= TT) return;
    int sv, dv;
    if (t < EE) { sv = ei[t]; dv = ei[EE + t]; }
    else        { sv = dv = t - EE; }
    int pos = atomicAdd(&g_cursor[dv], 1);
    g_srcs[pos] = sv;
}

// ---------------- fp16 tensor-core GEMM + fused alpha/fp16 epilogue ---------
#define BM 128
#define BN 128
#define BK 32
#define LDAH (BK + 8)
#define LDBH (BN + 8)
#define ASZH (BM * LDAH)
#define BSZH (BK * LDBH)
#define LDC  (64 + 4)
#define SMEM_BYTES (2 * (ASZH + BSZH) * 2)

template <int LAYER>
__global__ void __launch_bounds__(256) k_gemm(const float* __restrict__ Aext,
                                              const float* __restrict__ B,
                                              const float* __restrict__ att_s,
                                              const float* __restrict__ att_d,
                                              int M, int K) {
    __shared__ __align__(16) char smbuf[SMEM_BYTES];
    __half* Ash = (__half*)smbuf;
    __half* Bsh = (__half*)(smbuf + 2 * ASZH * 2);

    const int tid = threadIdx.x;
    const int wid = tid >> 5;
    const int wm = wid >> 1;
    const int wn = wid & 1;
    const int m0 = blockIdx.y * BM;
    const int n0 = blockIdx.x * BN;

    const int brow[4] = { (tid + 0) >> 5, (tid + 256) >> 5, (tid + 512) >> 5, (tid + 768) >> 5 };
    const int bcol = (tid & 31) * 4;
    float4 rbf[4];

    const int arow_f[4] = { (tid + 0) >> 3, (tid + 256) >> 3, (tid + 512) >> 3, (tid + 768) >> 3 };
    const int acol_f = (tid & 7) * 4;
    float4 raf[4];
    const int arow_h[2] = { (tid + 0) >> 2, (tid + 256) >> 2 };
    const int acol_h = (tid & 3) * 8;
    uint4 rah[2];

    auto loadG = [&](int k0) {
        if (LAYER == 1) {
#pragma unroll
            for (int i = 0; i < 4; i++) {
                float4 v = make_float4(0.f, 0.f, 0.f, 0.f);
                if (m0 + arow_f[i] < M)
                    v = *(const float4*)&Aext[(size_t)(m0 + arow_f[i]) * K + k0 + acol_f];
                raf[i] = v;
            }
        } else {
#pragma unroll
            for (int i = 0; i < 2; i++)
                rah[i] = *(const uint4*)&g_x1h[(size_t)(m0 + arow_h[i]) * K + k0 + acol_h];
        }
#pragma unroll
        for (int i = 0; i < 4; i++)
            rbf[i] = *(const float4*)&B[(size_t)(k0 + brow[i]) * CHN + n0 + bcol];
    };
    auto storeS = [&](int buf) {
        if (LAYER == 1) {
#pragma unroll
            for (int i = 0; i < 4; i++) {
                __half2* p = (__half2*)&Ash[buf * ASZH + arow_f[i] * LDAH + acol_f];
                p[0] = __floats2half2_rn(raf[i].x, raf[i].y);
                p[1] = __floats2half2_rn(raf[i].z, raf[i].w);
            }
        } else {
#pragma unroll
            for (int i = 0; i < 2; i++)
                *(uint4*)&Ash[buf * ASZH + arow_h[i] * LDAH + acol_h] = rah[i];
        }
#pragma unroll
        for (int i = 0; i < 4; i++) {
            __half2* p = (__half2*)&Bsh[buf * BSZH + brow[i] * LDBH + bcol];
            p[0] = __floats2half2_rn(rbf[i].x, rbf[i].y);
            p[1] = __floats2half2_rn(rbf[i].z, rbf[i].w);
        }
    };

    wmma::fragment<wmma::accumulator, 16, 16, 16, float> c[2][4];
#pragma unroll
    for (int i = 0; i < 2; i++)
#pragma unroll
        for (int j = 0; j < 4; j++) wmma::fill_fragment(c[i][j], 0.f);

    loadG(0);
    storeS(0);
    __syncthreads();

    int buf = 0;
    for (int k0 = 0; k0 < K; k0 += BK) {
        const bool has_next = (k0 + BK) < K;
        if (has_next) loadG(k0 + BK);

#pragma unroll
        for (int kk = 0; kk < BK; kk += 16) {
            wmma::fragment<wmma::matrix_a, 16, 16, 16, __half, wmma::row_major> a[2];
            wmma::fragment<wmma::matrix_b, 16, 16, 16, __half, wmma::row_major> b[4];
#pragma unroll
            for (int i = 0; i < 2; i++)
                wmma::load_matrix_sync(a[i], &Ash[buf * ASZH + (wm * 32 + i * 16) * LDAH + kk], LDAH);
#pragma unroll
            for (int j = 0; j < 4; j++)
                wmma::load_matrix_sync(b[j], &Bsh[buf * BSZH + kk * LDBH + wn * 64 + j * 16], LDBH);
#pragma unroll
            for (int i = 0; i < 2; i++)
#pragma unroll
                for (int j = 0; j < 4; j++)
                    wmma::mma_sync(c[i][j], a[i], b[j], c[i][j]);
        }

        if (has_next) {
            storeS(buf ^ 1);
            __syncthreads();
            buf ^= 1;
        }
    }

    // ---- epilogue: two 64-col chunks (each = one head) through smem ----
    float* Cs = (float*)smbuf;
    const int r = tid >> 1;
    const int half = tid & 1;
#pragma unroll
    for (int chunk = 0; chunk < 2; chunk++) {
        __syncthreads();
        if (wn == chunk) {
#pragma unroll
            for (int i = 0; i < 2; i++)
#pragma unroll
                for (int j = 0; j < 4; j++)
                    wmma::store_matrix_sync(
                        &Cs[(wm * 32 + i * 16) * LDC + j * 16],
                        c[i][j], LDC, wmma::mem_row_major);
        }
        __syncthreads();

        const float* crow = &Cs[r * LDC + half * 32];
        const int nbase = n0 + chunk * 64;

        uint4 w[4];
        __half2* wh = (__half2*)w;
#pragma unroll
        for (int i = 0; i < 16; i++)
            wh[i] = __floats2half2_rn(crow[2 * i], crow[2 * i + 1]);
        uint4* dst = (uint4*)&g_h16[(size_t)(m0 + r) * CHN + nbase + half * 32];
#pragma unroll
        for (int i = 0; i < 4; i++) dst[i] = w[i];

        const int hh = nbase >> 6;
        const float* asp = att_s + nbase + half * 32;
        const float* adp = att_d + nbase + half * 32;
        float s = 0.f, d = 0.f;
#pragma unroll
        for (int cc = 0; cc < 32; cc++) {
            float v = crow[cc];
            s += v * asp[cc];
            d += v * adp[cc];
        }
        s += __shfl_xor_sync(0xffffffffu, s, 1);
        d += __shfl_xor_sync(0xffffffffu, d, 1);
        if (half == 0 && m0 + r < NN) {
            g_as[(m0 + r) * 4 + hh] = s;
            g_ad[(m0 + r) * 4 + hh] = d;
        }
    }
}

// ---------------- fused edge + online-softmax + aggregation (warp/node) -----
// SMEM edge cache: (e float4, src) per edge for j < ECAP; spill to g_e beyond.
__device__ __forceinline__ float lrelu(float v) { return v > 0.f ? v : 0.2f * v; }

__device__ __forceinline__ void online_upd(float& m, float& s, float e) {
    float mn = fmaxf(m, e);
    s = s * __expf(m - mn) + __expf(e - mn);
    m = mn;
}
__device__ __forceinline__ void online_red(float& m, float& s, int o) {
    float mo = __shfl_xor_sync(0xffffffffu, m, o);
    float so = __shfl_xor_sync(0xffffffffu, s, o);
    float mn = fmaxf(m, mo);
    s = s * __expf(m - mn) + so * __expf(mo - mn);
    m = mn;
}

template <int LAYER>
__global__ void __launch_bounds__(256) k_agg(const float* __restrict__ bias,
                                             float* __restrict__ outext) {
    __shared__ __align__(16) float s_e[8][ECAP][4];   // 8 KB
    __shared__ int s_src[8][ECAP];                    // 2 KB
    const int wslot = threadIdx.x >> 5;

    const int gw = (blockIdx.x * blockDim.x + threadIdx.x) >> 5;
    const int lane = threadIdx.x & 31;
    if (gw >= NN) return;
    const int row = g_rowptr[gw];
    const int deg = g_rowptr[gw + 1] - row;

    const float4 ad4 = *(const float4*)&g_ad[gw * 4];

    // pass 1: inline logits; cache in SMEM (spill to g_e); online softmax stats
    float4 m4 = make_float4(-1e30f, -1e30f, -1e30f, -1e30f);
    float4 s4 = make_float4(0.f, 0.f, 0.f, 0.f);
    for (int j = lane; j < deg; j += 32) {
        const int sv = g_srcs[row + j];
        const float4 as = *(const float4*)&g_as[sv * 4];
        float4 e;
        e.x = lrelu(as.x + ad4.x);
        e.y = lrelu(as.y + ad4.y);
        e.z = lrelu(as.z + ad4.z);
        e.w = lrelu(as.w + ad4.w);
        if (j < ECAP) {
            *(float4*)&s_e[wslot][j][0] = e;
            s_src[wslot][j] = sv;
        } else {
            *(float4*)&g_e[(size_t)(row + j) * 4] = e;
        }
        online_upd(m4.x, s4.x, e.x);
        online_upd(m4.y, s4.y, e.y);
        online_upd(m4.z, s4.z, e.z);
        online_upd(m4.w, s4.w, e.w);
    }
#pragma unroll
    for (int o = 16; o; o >>= 1) {
        online_red(m4.x, s4.x, o);
        online_red(m4.y, s4.y, o);
        online_red(m4.z, s4.z, o);
        online_red(m4.w, s4.w, o);
    }
    __syncwarp();

    // pass 2: lane owns 8 contiguous halfs (one head)
    const int head = lane >> 3;
    const float m = (head == 0) ? m4.x : (head == 1) ? m4.y : (head == 2) ? m4.z : m4.w;
    const float sd = (head == 0) ? s4.x : (head == 1) ? s4.y : (head == 2) ? s4.z : s4.w;
    const float inv = 1.f / (sd + 1e-16f);
    const int cb = lane * 8;

    float acc[8];
#pragma unroll
    for (int k = 0; k < 8; k++) acc[k] = 0.f;

    const int degc = min(deg, ECAP);
#pragma unroll 2
    for (int j = 0; j < degc; j++) {
        const float e = s_e[wslot][j][head];
        const int src = s_src[wslot][j];
        const float a = __expf(e - m) * inv;
        const uint4 u = *(const uint4*)&g_h16[(size_t)src * CHN + cb];
        const __half2* hp = (const __half2*)&u;
#pragma unroll
        for (int k = 0; k < 4; k++) {
            const float2 f = __half22float2(hp[k]);
            acc[2 * k]     += a * f.x;
            acc[2 * k + 1] += a * f.y;
        }
    }
    for (int j = ECAP; j < deg; j++) {      // spill path (rare)
        const float e = g_e[(size_t)(row + j) * 4 + head];
        const int src = g_srcs[row + j];
        const float a = __expf(e - m) * inv;
        const uint4 u = *(const uint4*)&g_h16[(size_t)src * CHN + cb];
        const __half2* hp = (const __half2*)&u;
#pragma unroll
        for (int k = 0; k < 4; k++) {
            const float2 f = __half22float2(hp[k]);
            acc[2 * k]     += a * f.x;
            acc[2 * k + 1] += a * f.y;
        }
    }

    if (LAYER == 1) {
        const float4 b0 = *(const float4*)&bias[cb];
        const float4 b1 = *(const float4*)&bias[cb + 4];
        uint4 o;
        __half2* oh = (__half2*)&o;
        oh[0] = __floats2half2_rn(fmaxf(acc[0] + b0.x, 0.f), fmaxf(acc[1] + b0.y, 0.f));
        oh[1] = __floats2half2_rn(fmaxf(acc[2] + b0.z, 0.f), fmaxf(acc[3] + b0.w, 0.f));
        oh[2] = __floats2half2_rn(fmaxf(acc[4] + b1.x, 0.f), fmaxf(acc[5] + b1.y, 0.f));
        oh[3] = __floats2half2_rn(fmaxf(acc[6] + b1.z, 0.f), fmaxf(acc[7] + b1.w, 0.f));
        *(uint4*)&g_x1h[(size_t)gw * CHN + cb] = o;
    } else {
#pragma unroll
        for (int k = 0; k < 8; k++) {
            acc[k] += __shfl_xor_sync(0xffffffffu, acc[k], 8);
            acc[k] += __shfl_xor_sync(0xffffffffu, acc[k], 16);
        }
        if (lane < 8) {
            const int c = lane * 8;
            const float4 b0 = *(const float4*)&bias[c];
            const float4 b1 = *(const float4*)&bias[c + 4];
            float4 o0, o1;
            o0.x = 0.25f * acc[0] + b0.x;
            o0.y = 0.25f * acc[1] + b0.y;
            o0.z = 0.25f * acc[2] + b0.z;
            o0.w = 0.25f * acc[3] + b0.w;
            o1.x = 0.25f * acc[4] + b1.x;
            o1.y = 0.25f * acc[5] + b1.y;
            o1.z = 0.25f * acc[6] + b1.z;
            o1.w = 0.25f * acc[7] + b1.w;
            *(float4*)&outext[(size_t)gw * C2 + c] = o0;
            *(float4*)&outext[(size_t)gw * C2 + c + 4] = o1;
        }
    }
}

// ---------------- launch -----------------------------------------------------
extern "C" void kernel_launch(void* const* d_in, const int* in_sizes, int n_in,
                              void* d_out, int out_size) {
    const float* x   = (const float*)d_in[0];
    const int*   ei  = (const int*)d_in[1];
    const float* W1  = (const float*)d_in[2];
    const float* as1 = (const float*)d_in[3];
    const float* ad1 = (const float*)d_in[4];
    const float* b1  = (const float*)d_in[5];
    const float* W2  = (const float*)d_in[6];
    const float* as2 = (const float*)d_in[7];
    const float* ad2 = (const float*)d_in[8];
    const float* b2  = (const float*)d_in[9];
    float* out = (float*)d_out;

    dim3 gemm_grid(CHN / BN, NPAD / BM);
    const int agg_blocks = (NN * 32 + 255) / 256;

    // fork: GEMM-1 on side stream, CSR build on main stream (independent)
    cudaEventRecord(g_str.fork, 0);
    cudaStreamWaitEvent(g_str.s2, g_str.fork, 0);
    k_gemm<1><<<gemm_grid, 256, 0, g_str.s2>>>(x, W1, as1, ad1, NN, 128);
    cudaEventRecord(g_str.join, g_str.s2);

    k_zero_deg<<<(NN + 255) / 256, 256>>>();
    k_hist<<<(TT + 255) / 256, 256>>>(ei);
    k_scan1<<<SCAN_BLKS, 256>>>();
    k_scan2<<<1, 256>>>();
    k_scan3<<<SCAN_BLKS, 256>>>();
    k_scatter<<<(TT + 255) / 256, 256>>>(ei);

    // join: agg<1> needs CSR (main) + GEMM-1 (s2)
    cudaStreamWaitEvent(0, g_str.join, 0);
    k_agg<1><<<agg_blocks, 256>>>(b1, nullptr);

    // ----- layer 2 (serial chain) -----
    k_gemm<2><<<gemm_grid, 256>>>(nullptr, W2, as2, ad2, NN, 256);
    k_agg<2><<<agg_blocks, 256>>>(b2, out);
}

// round 16
// speedup vs baseline: 1.0541x; 1.0165x over previous
#include <cuda_runtime.h>
#include <cuda_fp16.h>
#include <mma.h>
using namespace nvcuda;

#define NN 50000
#define NPAD 50048     // NN rounded up to 128 (GEMM tile)
#define EE 800000
#define TT (EE + NN)
#define HH 4
#define CHN 256        // H * C (both layers)
#define C2  64
#define SCAN_BLKS 196  // 196*256 = 50176 >= NN
#define ECAP 64        // per-warp SMEM edge cache (spill to g_e beyond)

// ---------------- scratch (device globals; no allocation allowed) ----------
__device__ __align__(16) __half g_h16[(size_t)NPAD * CHN];  // GEMM out (fp16)
__device__ __align__(16) __half g_x1h[(size_t)NPAD * CHN];  // relu(layer1 out), fp16
__device__ __align__(16) __half g_w2h[CHN * CHN];           // W2 pre-converted fp16
__device__ __align__(16) float g_as[NN * HH];
__device__ __align__(16) float g_ad[NN * HH];
__device__ __align__(16) float g_e[(size_t)TT * HH];        // spill only (deg > ECAP)
__device__ int   g_deg[NN];     // BSS zero at load; re-zeroed by k_scan3 each replay
__device__ int   g_epos[TT];    // within-dst position from hist's atomicAdd
__device__ int   g_pref[NN];
__device__ int   g_bsum[SCAN_BLKS];
__device__ int   g_boff[SCAN_BLKS];
__device__ int   g_rowptr[NN + 1];
__device__ int   g_srcs[TT];

// ---------------- streams for fork/join overlap (static init, never freed) --
struct StreamsInit {
    cudaStream_t s2;
    cudaEvent_t fork, join;
    StreamsInit() {
        cudaStreamCreateWithFlags(&s2, cudaStreamNonBlocking);
        cudaEventCreateWithFlags(&fork, cudaEventDisableTiming);
        cudaEventCreateWithFlags(&join, cudaEventDisableTiming);
    }
};
static StreamsInit g_str;

// ---------------- W2 fp32 -> fp16 (off critical path, side stream) ----------
__global__ void k_cvtW(const float* __restrict__ W2) {
    const int i = (blockIdx.x * blockDim.x + threadIdx.x) * 4;
    if (i < CHN * CHN) {
        const float4 v = *(const float4*)&W2[i];
        __half2* p = (__half2*)&g_w2h[i];
        p[0] = __floats2half2_rn(v.x, v.y);
        p[1] = __floats2half2_rn(v.z, v.w);
    }
}

// ---------------- CSR build (single-atomic scheme) ---------------------------
__global__ void k_hist(const int* __restrict__ ei) {
    int t = blockIdx.x * blockDim.x + threadIdx.x;
    if (t >= TT) return;
    int d = (t < EE) ? ei[EE + t] : (t - EE);
    g_epos[t] = atomicAdd(&g_deg[d], 1);
}

__global__ void k_scan1() {
    __shared__ int s[256];
    const int tid = threadIdx.x;
    const int i = blockIdx.x * 256 + tid;
    int v = (i < NN) ? g_deg[i] : 0;
    s[tid] = v;
    __syncthreads();
#pragma unroll
    for (int off = 1; off < 256; off <<= 1) {
        int t = (tid >= off) ? s[tid - off] : 0;
        __syncthreads();
        s[tid] += t;
        __syncthreads();
    }
    if (i < NN) g_pref[i] = s[tid] - v;
    if (tid == 255) g_bsum[blockIdx.x] = s[255];
}

__global__ void k_scan2() {
    __shared__ int s[SCAN_BLKS];
    const int tid = threadIdx.x;
    int v = (tid < SCAN_BLKS) ? g_bsum[tid] : 0;
    if (tid < SCAN_BLKS) s[tid] = v;
    __syncthreads();
    for (int off = 1; off < SCAN_BLKS; off <<= 1) {
        int t = (tid >= off && tid < SCAN_BLKS) ? s[tid - off] : 0;
        __syncthreads();
        if (tid < SCAN_BLKS) s[tid] += t;
        __syncthreads();
    }
    if (tid < SCAN_BLKS) g_boff[tid] = s[tid] - v;
    if (tid == SCAN_BLKS - 1) g_rowptr[NN] = s[SCAN_BLKS - 1];
}

__global__ void k_scan3() {
    const int i = blockIdx.x * 256 + threadIdx.x;
    if (i < NN) {
        g_rowptr[i] = g_pref[i] + g_boff[blockIdx.x];
        g_deg[i] = 0;    // re-zero for the next graph replay
    }
}

__global__ void k_scatter(const int* __restrict__ ei) {
    int t = blockIdx.x * blockDim.x + threadIdx.x;
    if (t >= TT) return;
    int sv, dv;
    if (t < EE) { sv = ei[t]; dv = ei[EE + t]; }
    else        { sv = dv = t - EE; }
    g_srcs[g_rowptr[dv] + g_epos[t]] = sv;
}

// ---------------- fp16 tensor-core GEMM + fused alpha/fp16 epilogue ---------
#define BM 128
#define BN 128
#define BK 32
#define LDAH (BK + 8)
#define LDBH (BN + 8)
#define ASZH (BM * LDAH)
#define BSZH (BK * LDBH)
#define LDC  (64 + 4)
#define SMEM_BYTES (2 * (ASZH + BSZH) * 2)

template <int LAYER>
__global__ void __launch_bounds__(256) k_gemm(const float* __restrict__ Aext,
                                              const float* __restrict__ B,
                                              const float* __restrict__ att_s,
                                              const float* __restrict__ att_d,
                                              int M, int K) {
    __shared__ __align__(16) char smbuf[SMEM_BYTES];
    __half* Ash = (__half*)smbuf;
    __half* Bsh = (__half*)(smbuf + 2 * ASZH * 2);

    const int tid = threadIdx.x;
    const int wid = tid >> 5;
    const int wm = wid >> 1;
    const int wn = wid & 1;
    const int m0 = blockIdx.y * BM;
    const int n0 = blockIdx.x * BN;

    // B fp32 path (layer 1): 32x128 floats = 1024 float4 -> 4/thread
    const int brow_f[4] = { (tid + 0) >> 5, (tid + 256) >> 5, (tid + 512) >> 5, (tid + 768) >> 5 };
    const int bcol_f = (tid & 31) * 4;
    float4 rbf[4];
    // B fp16 path (layer 2): 32x128 halfs = 512 uint4 -> 2/thread
    const int brow_h[2] = { (tid + 0) >> 4, (tid + 256) >> 4 };
    const int bcol_h = (tid & 15) * 8;
    uint4 rbh[2];

    const int arow_f[4] = { (tid + 0) >> 3, (tid + 256) >> 3, (tid + 512) >> 3, (tid + 768) >> 3 };
    const int acol_f = (tid & 7) * 4;
    float4 raf[4];
    const int arow_h[2] = { (tid + 0) >> 2, (tid + 256) >> 2 };
    const int acol_h = (tid & 3) * 8;
    uint4 rah[2];

    auto loadG = [&](int k0) {
        if (LAYER == 1) {
#pragma unroll
            for (int i = 0; i < 4; i++) {
                float4 v = make_float4(0.f, 0.f, 0.f, 0.f);
                if (m0 + arow_f[i] < M)
                    v = *(const float4*)&Aext[(size_t)(m0 + arow_f[i]) * K + k0 + acol_f];
                raf[i] = v;
            }
#pragma unroll
            for (int i = 0; i < 4; i++)
                rbf[i] = *(const float4*)&B[(size_t)(k0 + brow_f[i]) * CHN + n0 + bcol_f];
        } else {
#pragma unroll
            for (int i = 0; i < 2; i++)
                rah[i] = *(const uint4*)&g_x1h[(size_t)(m0 + arow_h[i]) * K + k0 + acol_h];
#pragma unroll
            for (int i = 0; i < 2; i++)
                rbh[i] = *(const uint4*)&g_w2h[(size_t)(k0 + brow_h[i]) * CHN + n0 + bcol_h];
        }
    };
    auto storeS = [&](int buf) {
        if (LAYER == 1) {
#pragma unroll
            for (int i = 0; i < 4; i++) {
                __half2* p = (__half2*)&Ash[buf * ASZH + arow_f[i] * LDAH + acol_f];
                p[0] = __floats2half2_rn(raf[i].x, raf[i].y);
                p[1] = __floats2half2_rn(raf[i].z, raf[i].w);
            }
#pragma unroll
            for (int i = 0; i < 4; i++) {
                __half2* p = (__half2*)&Bsh[buf * BSZH + brow_f[i] * LDBH + bcol_f];
                p[0] = __floats2half2_rn(rbf[i].x, rbf[i].y);
                p[1] = __floats2half2_rn(rbf[i].z, rbf[i].w);
            }
        } else {
#pragma unroll
            for (int i = 0; i < 2; i++)
                *(uint4*)&Ash[buf * ASZH + arow_h[i] * LDAH + acol_h] = rah[i];
#pragma unroll
            for (int i = 0; i < 2; i++)
                *(uint4*)&Bsh[buf * BSZH + brow_h[i] * LDBH + bcol_h] = rbh[i];
        }
    };

    wmma::fragment<wmma::accumulator, 16, 16, 16, float> c[2][4];
#pragma unroll
    for (int i = 0; i < 2; i++)
#pragma unroll
        for (int j = 0; j < 4; j++) wmma::fill_fragment(c[i][j], 0.f);

    loadG(0);
    storeS(0);
    __syncthreads();

    int buf = 0;
    for (int k0 = 0; k0 < K; k0 += BK) {
        const bool has_next = (k0 + BK) < K;
        if (has_next) loadG(k0 + BK);

#pragma unroll
        for (int kk = 0; kk < BK; kk += 16) {
            wmma::fragment<wmma::matrix_a, 16, 16, 16, __half, wmma::row_major> a[2];
            wmma::fragment<wmma::matrix_b, 16, 16, 16, __half, wmma::row_major> b[4];
#pragma unroll
            for (int i = 0; i < 2; i++)
                wmma::load_matrix_sync(a[i], &Ash[buf * ASZH + (wm * 32 + i * 16) * LDAH + kk], LDAH);
#pragma unroll
            for (int j = 0; j < 4; j++)
                wmma::load_matrix_sync(b[j], &Bsh[buf * BSZH + kk * LDBH + wn * 64 + j * 16], LDBH);
#pragma unroll
            for (int i = 0; i < 2; i++)
#pragma unroll
                for (int j = 0; j < 4; j++)
                    wmma::mma_sync(c[i][j], a[i], b[j], c[i][j]);
        }

        if (has_next) {
            storeS(buf ^ 1);
            __syncthreads();
            buf ^= 1;
        }
    }

    // ---- epilogue: two 64-col chunks (each = one head) through smem ----
    float* Cs = (float*)smbuf;
    const int r = tid >> 1;
    const int half = tid & 1;
#pragma unroll
    for (int chunk = 0; chunk < 2; chunk++) {
        __syncthreads();
        if (wn == chunk) {
#pragma unroll
            for (int i = 0; i < 2; i++)
#pragma unroll
                for (int j = 0; j < 4; j++)
                    wmma::store_matrix_sync(
                        &Cs[(wm * 32 + i * 16) * LDC + j * 16],
                        c[i][j], LDC, wmma::mem_row_major);
        }
        __syncthreads();

        const float* crow = &Cs[r * LDC + half * 32];
        const int nbase = n0 + chunk * 64;

        uint4 w[4];
        __half2* wh = (__half2*)w;
#pragma unroll
        for (int i = 0; i < 16; i++)
            wh[i] = __floats2half2_rn(crow[2 * i], crow[2 * i + 1]);
        uint4* dst = (uint4*)&g_h16[(size_t)(m0 + r) * CHN + nbase + half * 32];
#pragma unroll
        for (int i = 0; i < 4; i++) dst[i] = w[i];

        const int hh = nbase >> 6;
        const float* asp = att_s + nbase + half * 32;
        const float* adp = att_d + nbase + half * 32;
        float s = 0.f, d = 0.f;
#pragma unroll
        for (int cc = 0; cc < 32; cc++) {
            float v = crow[cc];
            s += v * asp[cc];
            d += v * adp[cc];
        }
        s += __shfl_xor_sync(0xffffffffu, s, 1);
        d += __shfl_xor_sync(0xffffffffu, d, 1);
        if (half == 0 && m0 + r < NN) {
            g_as[(m0 + r) * 4 + hh] = s;
            g_ad[(m0 + r) * 4 + hh] = d;
        }
    }
}

// ---------------- fused edge + online-softmax + aggregation (warp/node) -----
__device__ __forceinline__ float lrelu(float v) { return v > 0.f ? v : 0.2f * v; }

__device__ __forceinline__ void online_upd(float& m, float& s, float e) {
    float mn = fmaxf(m, e);
    s = s * __expf(m - mn) + __expf(e - mn);
    m = mn;
}
__device__ __forceinline__ void online_red(float& m, float& s, int o) {
    float mo = __shfl_xor_sync(0xffffffffu, m, o);
    float so = __shfl_xor_sync(0xffffffffu, s, o);
    float mn = fmaxf(m, mo);
    s = s * __expf(m - mn) + so * __expf(mo - mn);
    m = mn;
}

template <int LAYER>
__global__ void __launch_bounds__(256) k_agg(const float* __restrict__ bias,
                                             float* __restrict__ outext) {
    __shared__ __align__(16) float s_e[8][ECAP][4];
    __shared__ int s_src[8][ECAP];
    const int wslot = threadIdx.x >> 5;

    const int gw = (blockIdx.x * blockDim.x + threadIdx.x) >> 5;
    const int lane = threadIdx.x & 31;
    if (gw >= NN) return;
    const int row = g_rowptr[gw];
    const int deg = g_rowptr[gw + 1] - row;

    const float4 ad4 = *(const float4*)&g_ad[gw * 4];

    float4 m4 = make_float4(-1e30f, -1e30f, -1e30f, -1e30f);
    float4 s4 = make_float4(0.f, 0.f, 0.f, 0.f);
    for (int j = lane; j < deg; j += 32) {
        const int sv = g_srcs[row + j];
        const float4 as = *(const float4*)&g_as[sv * 4];
        float4 e;
        e.x = lrelu(as.x + ad4.x);
        e.y = lrelu(as.y + ad4.y);
        e.z = lrelu(as.z + ad4.z);
        e.w = lrelu(as.w + ad4.w);
        if (j < ECAP) {
            *(float4*)&s_e[wslot][j][0] = e;
            s_src[wslot][j] = sv;
        } else {
            *(float4*)&g_e[(size_t)(row + j) * 4] = e;
        }
        online_upd(m4.x, s4.x, e.x);
        online_upd(m4.y, s4.y, e.y);
        online_upd(m4.z, s4.z, e.z);
        online_upd(m4.w, s4.w, e.w);
    }
#pragma unroll
    for (int o = 16; o; o >>= 1) {
        online_red(m4.x, s4.x, o);
        online_red(m4.y, s4.y, o);
        online_red(m4.z, s4.z, o);
        online_red(m4.w, s4.w, o);
    }
    __syncwarp();

    const int head = lane >> 3;
    const float m = (head == 0) ? m4.x : (head == 1) ? m4.y : (head == 2) ? m4.z : m4.w;
    const float sd = (head == 0) ? s4.x : (head == 1) ? s4.y : (head == 2) ? s4.z : s4.w;
    const float inv = 1.f / (sd + 1e-16f);
    const int cb = lane * 8;

    float acc[8];
#pragma unroll
    for (int k = 0; k < 8; k++) acc[k] = 0.f;

    const int degc = min(deg, ECAP);
#pragma unroll 2
    for (int j = 0; j < degc; j++) {
        const float e = s_e[wslot][j][head];
        const int src = s_src[wslot][j];
        const float a = __expf(e - m) * inv;
        const uint4 u = *(const uint4*)&g_h16[(size_t)src * CHN + cb];
        const __half2* hp = (const __half2*)&u;
#pragma unroll
        for (int k = 0; k < 4; k++) {
            const float2 f = __half22float2(hp[k]);
            acc[2 * k]     += a * f.x;
            acc[2 * k + 1] += a * f.y;
        }
    }
    for (int j = ECAP; j < deg; j++) {
        const float e = g_e[(size_t)(row + j) * 4 + head];
        const int src = g_srcs[row + j];
        const float a = __expf(e - m) * inv;
        const uint4 u = *(const uint4*)&g_h16[(size_t)src * CHN + cb];
        const __half2* hp = (const __half2*)&u;
#pragma unroll
        for (int k = 0; k < 4; k++) {
            const float2 f = __half22float2(hp[k]);
            acc[2 * k]     += a * f.x;
            acc[2 * k + 1] += a * f.y;
        }
    }

    if (LAYER == 1) {
        const float4 b0 = *(const float4*)&bias[cb];
        const float4 b1 = *(const float4*)&bias[cb + 4];
        uint4 o;
        __half2* oh = (__half2*)&o;
        oh[0] = __floats2half2_rn(fmaxf(acc[0] + b0.x, 0.f), fmaxf(acc[1] + b0.y, 0.f));
        oh[1] = __floats2half2_rn(fmaxf(acc[2] + b0.z, 0.f), fmaxf(acc[3] + b0.w, 0.f));
        oh[2] = __floats2half2_rn(fmaxf(acc[4] + b1.x, 0.f), fmaxf(acc[5] + b1.y, 0.f));
        oh[3] = __floats2half2_rn(fmaxf(acc[6] + b1.z, 0.f), fmaxf(acc[7] + b1.w, 0.f));
        *(uint4*)&g_x1h[(size_t)gw * CHN + cb] = o;
    } else {
#pragma unroll
        for (int k = 0; k < 8; k++) {
            acc[k] += __shfl_xor_sync(0xffffffffu, acc[k], 8);
            acc[k] += __shfl_xor_sync(0xffffffffu, acc[k], 16);
        }
        if (lane < 8) {
            const int c = lane * 8;
            const float4 b0 = *(const float4*)&bias[c];
            const float4 b1 = *(const float4*)&bias[c + 4];
            float4 o0, o1;
            o0.x = 0.25f * acc[0] + b0.x;
            o0.y = 0.25f * acc[1] + b0.y;
            o0.z = 0.25f * acc[2] + b0.z;
            o0.w = 0.25f * acc[3] + b0.w;
            o1.x = 0.25f * acc[4] + b1.x;
            o1.y = 0.25f * acc[5] + b1.y;
            o1.z = 0.25f * acc[6] + b1.z;
            o1.w = 0.25f * acc[7] + b1.w;
            *(float4*)&outext[(size_t)gw * C2 + c] = o0;
            *(float4*)&outext[(size_t)gw * C2 + c + 4] = o1;
        }
    }
}

// ---------------- launch -----------------------------------------------------
extern "C" void kernel_launch(void* const* d_in, const int* in_sizes, int n_in,
                              void* d_out, int out_size) {
    const float* x   = (const float*)d_in[0];
    const int*   ei  = (const int*)d_in[1];
    const float* W1  = (const float*)d_in[2];
    const float* as1 = (const float*)d_in[3];
    const float* ad1 = (const float*)d_in[4];
    const float* b1  = (const float*)d_in[5];
    const float* W2  = (const float*)d_in[6];
    const float* as2 = (const float*)d_in[7];
    const float* ad2 = (const float*)d_in[8];
    const float* b2  = (const float*)d_in[9];
    float* out = (float*)d_out;

    dim3 gemm_grid(CHN / BN, NPAD / BM);
    const int agg_blocks = (NN * 32 + 255) / 256;

    // fork: W2-convert + GEMM-1 on side stream; CSR build on main stream
    cudaEventRecord(g_str.fork, 0);
    cudaStreamWaitEvent(g_str.s2, g_str.fork, 0);
    k_cvtW<<<CHN * CHN / 4 / 256, 256, 0, g_str.s2>>>(W2);
    k_gemm<1><<<gemm_grid, 256, 0, g_str.s2>>>(x, W1, as1, ad1, NN, 128);
    cudaEventRecord(g_str.join, g_str.s2);

    k_hist<<<(TT + 255) / 256, 256>>>(ei);
    k_scan1<<<SCAN_BLKS, 256>>>();
    k_scan2<<<1, 256>>>();
    k_scan3<<<SCAN_BLKS, 256>>>();
    k_scatter<<<(TT + 255) / 256, 256>>>(ei);

    // join: agg<1> needs CSR (main) + GEMM-1 (s2)
    cudaStreamWaitEvent(0, g_str.join, 0);
    k_agg<1><<<agg_blocks, 256>>>(b1, nullptr);

    // ----- layer 2 (serial chain) -----
    k_gemm<2><<<gemm_grid, 256>>>(nullptr, nullptr, as2, ad2, NN, 256);
    k_agg<2><<<agg_blocks, 256>>>(b2, out);
}